// round 10
// baseline (speedup 1.0000x reference)
#include <cuda_runtime.h>

#define SIZE 512
#define NS 256
#define NT 128
#define KST4 132     // per-warp keep stride in float4 (264 float2 >= 256+4 sentinels)

__device__ __forceinline__ float fsqrt_approx(float x) {
    float r; asm("sqrt.approx.f32 %0, %1;" : "=f"(r) : "f"(x)); return r;
}
__device__ __forceinline__ float fexp2_approx(float x) {
    float r; asm("ex2.approx.f32 %0, %1;" : "=f"(r) : "f"(x)); return r;
}
__device__ __forceinline__ float flog2_approx(float x) {
    float r; asm("lg2.approx.f32 %0, %1;" : "=f"(r) : "f"(x)); return r;
}
__device__ __forceinline__ float frcp_approx(float x) {
    float r; asm("rcp.approx.f32 %0, %1;" : "=f"(r) : "f"(x)); return r;
}

// exp2 on the FMA pipe: z in [-100, 0], relative error ~5e-4
__device__ __forceinline__ float exp2_poly(float z) {
    const float MAGIC = 12582912.0f;            // 1.5 * 2^23
    const float rr = z + MAGIC;                 // RNE -> MAGIC + round(z)
    const int   n  = __float_as_int(rr) - 0x4B400000;   // round(z)
    const float f  = z - (float)n;              // f in [-0.5, 0.5]
    float p = fmaf(f, 0.0558263f, 0.2402265f);
    p = fmaf(f, p, 0.6931472f);
    p = fmaf(f, p, 1.0f);
    return __int_as_float((n + 127) << 23) * p; // 2^n * 2^f
}

// ---- fused kernel: 4 independent warps per CTA, one swizzled 8x4 tile per warp ----
__global__ __launch_bounds__(NT)
void glyph_kernel(const float* __restrict__ cp, float* __restrict__ out)
{
    __shared__ float4 samp[NS / 2];          // 256 samples as 128 float4 pairs
    __shared__ float4 keepbuf[4 * KST4];     // private segment per warp

    const int tid  = threadIdx.x;
    const int lane = tid & 31;
    const int w    = tid >> 5;

    // ---- per-CTA Bezier samples: thread t computes samples 2t and 2t+1 ----
    {
        const float4* cp4 = (const float4*)cp;
        const int stroke = tid >> 4;
        const float4 a = cp4[2 * stroke];
        const float4 b = cp4[2 * stroke + 1];
        const float q0x = __saturatef(a.x), q0y = __saturatef(a.y);
        const float q1x = __saturatef(a.z), q1y = __saturatef(a.w);
        const float q2x = __saturatef(b.x), q2y = __saturatef(b.y);
        const float q3x = __saturatef(b.z), q3y = __saturatef(b.w);
        const int j = (2 * tid) & 31;
        float4 o;
        {
            const float t  = (float)j * (1.0f / 31.0f);
            const float mt = 1.0f - t;
            const float w0 = mt * mt * mt, w1 = 3.0f * mt * mt * t;
            const float w2 = 3.0f * mt * t * t, w3 = t * t * t;
            o.x = w0 * q0x + w1 * q1x + w2 * q2x + w3 * q3x;
            o.y = w0 * q0y + w1 * q1y + w2 * q2y + w3 * q3y;
        }
        {
            const float t  = (float)(j + 1) * (1.0f / 31.0f);
            const float mt = 1.0f - t;
            const float w0 = mt * mt * mt, w1 = 3.0f * mt * mt * t;
            const float w2 = 3.0f * mt * t * t, w3 = t * t * t;
            o.z = w0 * q0x + w1 * q1x + w2 * q2x + w3 * q3x;
            o.w = w0 * q0y + w1 * q1y + w2 * q2y + w3 * q3y;
        }
        samp[tid] = o;
    }
    __syncthreads();
    // warps fully independent from here

    // swizzled warp-tile id: spread active tiles uniformly across SMs
    const int idx  = blockIdx.x * 4 + w;     // 0..8191
    const int tile = (idx * 2741) & 8191;    // odd multiplier -> bijection mod 8192
    const int x0 = (tile & 63) * 8;
    const int y0 = (tile >> 6) * 4;

    const float inv = 1.0f / 511.0f;
    const float cx = ((float)x0 + 3.5f) * inv;
    const float cy = ((float)y0 + 1.5f) * inv;
    const float r  = 0.0074617f + 1e-4f;     // 0.5*sqrt(7^2+3^2)/511

    // ---- 8 samples per lane: center dist^2 + warp-min ----
    float2 s[8];
    float  dc2[8];
    float  m = 1e30f;
    #pragma unroll
    for (int j = 0; j < 4; j++) {
        const float4 v = samp[j * 32 + lane];
        s[2 * j]     = make_float2(v.x, v.y);
        s[2 * j + 1] = make_float2(v.z, v.w);
        float ax = cx - v.x, ay = cy - v.y;
        dc2[2 * j] = fmaf(ax, ax, ay * ay);
        ax = cx - v.z; ay = cy - v.w;
        dc2[2 * j + 1] = fmaf(ax, ax, ay * ay);
        m = fminf(m, fminf(dc2[2 * j], dc2[2 * j + 1]));
    }
    #pragma unroll
    for (int off = 16; off; off >>= 1)
        m = fminf(m, __shfl_xor_sync(0xffffffffu, m, off));
    const float dcmin = sqrtf(m);

    const int px = x0 + (lane & 7);
    const int py = y0 + (lane >> 3);
    const int p  = py * SIZE + px;

    // ---- warp-tile skip: coverage < 2.3e-5 ----
    if (dcmin > 0.115f + r) {
        out[p] = 1.0f;
        return;
    }

    // ---- warp compaction: keep dc <= dcmin + 2r + 0.055 ----
    const float thr  = dcmin + 2.0f * r + 0.055f;
    const float thr2 = thr * thr;
    float2* kp = (float2*)(keepbuf + w * KST4);
    const unsigned lt = (1u << lane) - 1u;
    int c = 0;
    #pragma unroll
    for (int j = 0; j < 8; j++) {
        const bool k = (dc2[j] <= thr2);
        const unsigned msk = __ballot_sync(0xffffffffu, k);
        if (k) kp[c + __popc(msk & lt)] = s[j];
        c += __popc(msk);
    }
    if (lane < 4) kp[c + lane] = make_float2(100.0f, 100.0f);  // sentinels
    __syncwarp();
    const int nIt = ((c + 3) & ~3) >> 1;     // float4 iterations (even count)

    // ---- per-pixel single-pass soft-min; exp2 on FMA pipe, sqrt on MUFU ----
    const float gx = (float)px * inv;
    const float gy = (float)py * inv;
    const float NEGK = -369.3298503f;        // -256 * log2(e)
    const float4* kp4 = (const float4*)kp;
    float accA = 0.0f, accB = 0.0f;
    #pragma unroll 4
    for (int i = 0; i < nIt; i++) {
        const float4 q = kp4[i];             // broadcast LDS.128
        float ax = gx - q.x, ay = gy - q.y;
        const float dA = fsqrt_approx(fmaf(ax, ax, ay * ay));
        ax = gx - q.z; ay = gy - q.w;
        const float dB = fsqrt_approx(fmaf(ax, ax, ay * ay));
        const float zA = fmaxf(dA * NEGK, -100.0f);   // clamp handles sentinels
        const float zB = fmaxf(dB * NEGK, -100.0f);
        accA += exp2_poly(zA);
        accB += exp2_poly(zB);
    }

    const float md = flog2_approx(accA + accB) * (-0.69314718f / 256.0f);
    const float z  = (0.04f - md) * (200.0f * 1.44269504f);
    out[p] = frcp_approx(1.0f + fexp2_approx(z));
}

extern "C" void kernel_launch(void* const* d_in, const int* in_sizes, int n_in,
                              void* d_out, int out_size) {
    const float* cp = (const float*)d_in[0];   // control_points [8,4,2]
    float* out = (float*)d_out;
    glyph_kernel<<<2048, NT>>>(cp, out);       // 2048 CTAs x 4 swizzled warp-tiles
}

// round 11
// speedup vs baseline: 1.2007x; 1.2007x over previous
#include <cuda_runtime.h>

#define SIZE 512
#define NS 256
#define NT 128
#define KSTW 264       // per-warp keep-list floats per coord (256 + up to 8 sentinels)

#define KSCALE 369.3298503f   // 256 * log2(e); distances pre-scaled by this

__device__ __forceinline__ float fsqrt_approx(float x) {
    float r; asm("sqrt.approx.f32 %0, %1;" : "=f"(r) : "f"(x)); return r;
}
__device__ __forceinline__ float fexp2_approx(float x) {
    float r; asm("ex2.approx.f32 %0, %1;" : "=f"(r) : "f"(x)); return r;
}
__device__ __forceinline__ float flog2_approx(float x) {
    float r; asm("lg2.approx.f32 %0, %1;" : "=f"(r) : "f"(x)); return r;
}
__device__ __forceinline__ float frcp_approx(float x) {
    float r; asm("rcp.approx.f32 %0, %1;" : "=f"(r) : "f"(x)); return r;
}

// ---- fused kernel: 4 independent warps per CTA, one 8x4 tile per warp ----
__global__ __launch_bounds__(NT)
void glyph_kernel(const float* __restrict__ cp, float* __restrict__ out)
{
    __shared__ float4 samp[NS / 2];            // 256 K-scaled samples as float4 pairs
    __shared__ float  keepx[4][KSTW];          // per-warp SoA keep lists (K-scaled)
    __shared__ float  keepy[4][KSTW];

    const int tid  = threadIdx.x;
    const int lane = tid & 31;
    const int w    = tid >> 5;

    // ---- per-CTA Bezier samples (K-scaled): thread t computes samples 2t, 2t+1 ----
    {
        const float4* cp4 = (const float4*)cp;
        const int stroke = tid >> 4;
        const float4 a = cp4[2 * stroke];
        const float4 b = cp4[2 * stroke + 1];
        const float q0x = __saturatef(a.x), q0y = __saturatef(a.y);
        const float q1x = __saturatef(a.z), q1y = __saturatef(a.w);
        const float q2x = __saturatef(b.x), q2y = __saturatef(b.y);
        const float q3x = __saturatef(b.z), q3y = __saturatef(b.w);
        const int j = (2 * tid) & 31;
        float4 o;
        {
            const float t  = (float)j * (1.0f / 31.0f);
            const float mt = 1.0f - t;
            const float w0 = mt * mt * mt, w1 = 3.0f * mt * mt * t;
            const float w2 = 3.0f * mt * t * t, w3 = t * t * t;
            o.x = (w0 * q0x + w1 * q1x + w2 * q2x + w3 * q3x) * KSCALE;
            o.y = (w0 * q0y + w1 * q1y + w2 * q2y + w3 * q3y) * KSCALE;
        }
        {
            const float t  = (float)(j + 1) * (1.0f / 31.0f);
            const float mt = 1.0f - t;
            const float w0 = mt * mt * mt, w1 = 3.0f * mt * mt * t;
            const float w2 = 3.0f * mt * t * t, w3 = t * t * t;
            o.z = (w0 * q0x + w1 * q1x + w2 * q2x + w3 * q3x) * KSCALE;
            o.w = (w0 * q0y + w1 * q1y + w2 * q2y + w3 * q3y) * KSCALE;
        }
        samp[tid] = o;
    }
    __syncthreads();
    // warps fully independent from here

    const int tile = blockIdx.x * 4 + w;       // linear tile map (no swizzle)
    const int x0 = (tile & 63) * 8;
    const int y0 = (tile >> 6) * 4;

    const float inv = 1.0f / 511.0f;
    const float cxs = ((float)x0 + 3.5f) * inv * KSCALE;   // K-scaled tile center
    const float cys = ((float)y0 + 1.5f) * inv * KSCALE;
    const float R = 0.0074617f + 1e-4f;        // 0.5*sqrt(7^2+3^2)/511

    // ---- 8 samples per lane: scaled center dist^2 + warp-min ----
    float2 s[8];
    float  dc2[8];
    float  m = 1e30f;
    #pragma unroll
    for (int j = 0; j < 4; j++) {
        const float4 v = samp[j * 32 + lane];
        s[2 * j]     = make_float2(v.x, v.y);
        s[2 * j + 1] = make_float2(v.z, v.w);
        float ax = cxs - v.x, ay = cys - v.y;
        dc2[2 * j] = fmaf(ax, ax, ay * ay);
        ax = cxs - v.z; ay = cys - v.w;
        dc2[2 * j + 1] = fmaf(ax, ax, ay * ay);
        m = fminf(m, fminf(dc2[2 * j], dc2[2 * j + 1]));
    }
    #pragma unroll
    for (int off = 16; off; off >>= 1)
        m = fminf(m, __shfl_xor_sync(0xffffffffu, m, off));
    const float dcmin_s = sqrtf(m);            // = K * dcmin

    const int px = x0 + (lane & 7);
    const int py = y0 + (lane >> 3);
    const int p  = py * SIZE + px;

    // ---- warp-tile skip: coverage < 2.3e-5 ----
    if (dcmin_s > (0.115f + R) * KSCALE) {
        out[p] = 1.0f;
        return;
    }

    // ---- warp compaction (SoA): keep dc_s <= dcmin_s + (2R + 0.055)*K ----
    const float thr  = dcmin_s + (2.0f * R + 0.055f) * KSCALE;
    const float thr2 = thr * thr;
    float* kpx = keepx[w];
    float* kpy = keepy[w];
    const unsigned lt = (1u << lane) - 1u;
    int c = 0;
    #pragma unroll
    for (int j = 0; j < 8; j++) {
        const bool k = (dc2[j] <= thr2);
        const unsigned msk = __ballot_sync(0xffffffffu, k);
        if (k) {
            const int pos = c + __popc(msk & lt);
            kpx[pos] = s[j].x;
            kpy[pos] = s[j].y;
        }
        c += __popc(msk);
    }
    const int cpad = (c + 7) & ~7;             // pad to multiple of 8 samples
    if (lane < cpad - c) {                     // sentinels: ex2(-4e4) == 0
        kpx[c + lane] = 4.0e4f;
        kpy[c + lane] = 4.0e4f;
    }
    __syncwarp();
    const int nPair = cpad >> 1;               // 2 samples per iteration

    // ---- per-pixel single-pass soft-min, packed f32x2 distance math ----
    const float gxs = (float)px * inv * KSCALE;
    const float gys = (float)py * inv * KSCALE;
    unsigned long long GX, GY;
    asm("mov.b64 %0, {%1, %1};" : "=l"(GX) : "f"(gxs));
    asm("mov.b64 %0, {%1, %1};" : "=l"(GY) : "f"(gys));

    unsigned kxa = (unsigned)__cvta_generic_to_shared(kpx);
    unsigned kya = (unsigned)__cvta_generic_to_shared(kpy);

    float accA = 0.0f, accB = 0.0f;
    #pragma unroll 4
    for (int i = 0; i < nPair; i++) {
        unsigned long long X, Y, dx, dy, dy2, d2;
        asm("ld.shared.b64 %0, [%1];" : "=l"(X) : "r"(kxa + (i << 3)));
        asm("ld.shared.b64 %0, [%1];" : "=l"(Y) : "r"(kya + (i << 3)));
        asm("sub.rn.f32x2 %0, %1, %2;" : "=l"(dx) : "l"(GX), "l"(X));
        asm("sub.rn.f32x2 %0, %1, %2;" : "=l"(dy) : "l"(GY), "l"(Y));
        asm("mul.rn.f32x2 %0, %1, %2;" : "=l"(dy2) : "l"(dy), "l"(dy));
        asm("fma.rn.f32x2 %0, %1, %2, %3;" : "=l"(d2) : "l"(dx), "l"(dx), "l"(dy2));
        float d2A, d2B;
        asm("mov.b64 {%0, %1}, %2;" : "=f"(d2A), "=f"(d2B) : "l"(d2));
        const float dA = fsqrt_approx(d2A);    // = K * dist
        const float dB = fsqrt_approx(d2B);
        accA += fexp2_approx(-dA);             // exp(-256*dist)
        accB += fexp2_approx(-dB);
    }

    const float md = flog2_approx(accA + accB) * (-0.69314718f / 256.0f);
    const float z  = (0.04f - md) * (200.0f * 1.44269504f);
    out[p] = frcp_approx(1.0f + fexp2_approx(z));
}

extern "C" void kernel_launch(void* const* d_in, const int* in_sizes, int n_in,
                              void* d_out, int out_size) {
    const float* cp = (const float*)d_in[0];   // control_points [8,4,2]
    float* out = (float*)d_out;
    glyph_kernel<<<2048, NT>>>(cp, out);       // 2048 CTAs x 4 warp-tiles
}

// round 12
// speedup vs baseline: 1.2362x; 1.0295x over previous
#include <cuda_runtime.h>

#define SIZE 512
#define NS 256
#define NT 128
#define KSTW 264       // per-warp keep-list floats per coord (256 + up to 8 sentinels)

#define KSCALE 369.3298503f   // 256 * log2(e); distances pre-scaled by this

__device__ __forceinline__ float fsqrt_approx(float x) {
    float r; asm("sqrt.approx.f32 %0, %1;" : "=f"(r) : "f"(x)); return r;
}
__device__ __forceinline__ float fexp2_approx(float x) {
    float r; asm("ex2.approx.f32 %0, %1;" : "=f"(r) : "f"(x)); return r;
}
__device__ __forceinline__ float flog2_approx(float x) {
    float r; asm("lg2.approx.f32 %0, %1;" : "=f"(r) : "f"(x)); return r;
}
__device__ __forceinline__ float frcp_approx(float x) {
    float r; asm("rcp.approx.f32 %0, %1;" : "=f"(r) : "f"(x)); return r;
}

// exp2 on the FMA pipe. z in [-110, 0] (no clamp needed: sentinels give z ~ -100).
__device__ __forceinline__ float exp2_fma(float z) {
    const float MAGIC = 12582912.0f;                 // 1.5 * 2^23, ulp = 1
    const float rr = z + MAGIC;                      // RNE -> MAGIC + round(z)
    const int   n  = __float_as_int(rr) - 0x4B400000;
    const float f  = z - (rr - MAGIC);               // frac in [-0.5, 0.5], no I2F
    float p = fmaf(f, 0.0558263f, 0.2402265f);
    p = fmaf(f, p, 0.6931472f);
    p = fmaf(f, p, 1.0f);
    return __int_as_float((n + 127) << 23) * p;      // 2^n * 2^f
}

// ---- fused kernel: 4 independent warps per CTA, one 8x4 tile per warp ----
__global__ __launch_bounds__(NT)
void glyph_kernel(const float* __restrict__ cp, float* __restrict__ out)
{
    __shared__ float4 samp[NS / 2];            // 256 K-scaled samples as float4 pairs
    __shared__ float  keepx[4][KSTW];          // per-warp SoA keep lists (K-scaled)
    __shared__ float  keepy[4][KSTW];

    const int tid  = threadIdx.x;
    const int lane = tid & 31;
    const int w    = tid >> 5;

    // ---- per-CTA Bezier samples (K-scaled): thread t computes samples 2t, 2t+1 ----
    {
        const float4* cp4 = (const float4*)cp;
        const int stroke = tid >> 4;
        const float4 a = cp4[2 * stroke];
        const float4 b = cp4[2 * stroke + 1];
        const float q0x = __saturatef(a.x), q0y = __saturatef(a.y);
        const float q1x = __saturatef(a.z), q1y = __saturatef(a.w);
        const float q2x = __saturatef(b.x), q2y = __saturatef(b.y);
        const float q3x = __saturatef(b.z), q3y = __saturatef(b.w);
        const int j = (2 * tid) & 31;
        float4 o;
        {
            const float t  = (float)j * (1.0f / 31.0f);
            const float mt = 1.0f - t;
            const float w0 = mt * mt * mt, w1 = 3.0f * mt * mt * t;
            const float w2 = 3.0f * mt * t * t, w3 = t * t * t;
            o.x = (w0 * q0x + w1 * q1x + w2 * q2x + w3 * q3x) * KSCALE;
            o.y = (w0 * q0y + w1 * q1y + w2 * q2y + w3 * q3y) * KSCALE;
        }
        {
            const float t  = (float)(j + 1) * (1.0f / 31.0f);
            const float mt = 1.0f - t;
            const float w0 = mt * mt * mt, w1 = 3.0f * mt * mt * t;
            const float w2 = 3.0f * mt * t * t, w3 = t * t * t;
            o.z = (w0 * q0x + w1 * q1x + w2 * q2x + w3 * q3x) * KSCALE;
            o.w = (w0 * q0y + w1 * q1y + w2 * q2y + w3 * q3y) * KSCALE;
        }
        samp[tid] = o;
    }
    __syncthreads();
    // warps fully independent from here

    const int tile = blockIdx.x * 4 + w;       // linear tile map
    const int x0 = (tile & 63) * 8;
    const int y0 = (tile >> 6) * 4;

    const float inv = 1.0f / 511.0f;
    const float cxs = ((float)x0 + 3.5f) * inv * KSCALE;   // K-scaled tile center
    const float cys = ((float)y0 + 1.5f) * inv * KSCALE;
    const float R = 0.0074617f + 1e-4f;        // 0.5*sqrt(7^2+3^2)/511

    // ---- 8 samples per lane: scaled center dist^2 + warp-min ----
    float2 s[8];
    float  dc2[8];
    float  m = 1e30f;
    #pragma unroll
    for (int j = 0; j < 4; j++) {
        const float4 v = samp[j * 32 + lane];
        s[2 * j]     = make_float2(v.x, v.y);
        s[2 * j + 1] = make_float2(v.z, v.w);
        float ax = cxs - v.x, ay = cys - v.y;
        dc2[2 * j] = fmaf(ax, ax, ay * ay);
        ax = cxs - v.z; ay = cys - v.w;
        dc2[2 * j + 1] = fmaf(ax, ax, ay * ay);
        m = fminf(m, fminf(dc2[2 * j], dc2[2 * j + 1]));
    }
    #pragma unroll
    for (int off = 16; off; off >>= 1)
        m = fminf(m, __shfl_xor_sync(0xffffffffu, m, off));
    const float dcmin_s = sqrtf(m);            // = K * dcmin

    const int px = x0 + (lane & 7);
    const int py = y0 + (lane >> 3);
    const int p  = py * SIZE + px;

    // ---- warp-tile skip: coverage < 2.3e-5 ----
    if (dcmin_s > (0.115f + R) * KSCALE) {
        out[p] = 1.0f;
        return;
    }

    // ---- warp compaction (SoA): keep dc_s <= dcmin_s + (2R + 0.055)*K ----
    const float thr  = dcmin_s + (2.0f * R + 0.055f) * KSCALE;
    const float thr2 = thr * thr;
    float* kpx = keepx[w];
    float* kpy = keepy[w];
    const unsigned lt = (1u << lane) - 1u;
    int c = 0;
    #pragma unroll
    for (int j = 0; j < 8; j++) {
        const bool k = (dc2[j] <= thr2);
        const unsigned msk = __ballot_sync(0xffffffffu, k);
        if (k) {
            const int pos = c + __popc(msk & lt);
            kpx[pos] = s[j].x;
            kpy[pos] = s[j].y;
        }
        c += __popc(msk);
    }
    const int cpad = (c + 7) & ~7;             // pad to multiple of 8 samples
    if (lane < cpad - c) {                     // sentinels ~100 scaled units away:
        kpx[c + lane] = cxs + 100.0f;          //   z ~ -100 -> exp2_fma ~ 2^-100
        kpy[c + lane] = cys;
    }
    __syncwarp();
    const int nPair = cpad >> 1;               // 2 samples per iteration

    // ---- per-pixel single-pass soft-min: sqrt on MUFU, exp2 on FMA pipe ----
    const float gxs = (float)px * inv * KSCALE;
    const float gys = (float)py * inv * KSCALE;
    unsigned long long GX, GY;
    asm("mov.b64 %0, {%1, %1};" : "=l"(GX) : "f"(gxs));
    asm("mov.b64 %0, {%1, %1};" : "=l"(GY) : "f"(gys));

    unsigned kxa = (unsigned)__cvta_generic_to_shared(kpx);
    unsigned kya = (unsigned)__cvta_generic_to_shared(kpy);

    float accA = 0.0f, accB = 0.0f;
    #pragma unroll 4
    for (int i = 0; i < nPair; i++) {
        unsigned long long X, Y, dx, dy, dy2, d2;
        asm("ld.shared.b64 %0, [%1];" : "=l"(X) : "r"(kxa + (i << 3)));
        asm("ld.shared.b64 %0, [%1];" : "=l"(Y) : "r"(kya + (i << 3)));
        asm("sub.rn.f32x2 %0, %1, %2;" : "=l"(dx) : "l"(GX), "l"(X));
        asm("sub.rn.f32x2 %0, %1, %2;" : "=l"(dy) : "l"(GY), "l"(Y));
        asm("mul.rn.f32x2 %0, %1, %2;" : "=l"(dy2) : "l"(dy), "l"(dy));
        asm("fma.rn.f32x2 %0, %1, %2, %3;" : "=l"(d2) : "l"(dx), "l"(dx), "l"(dy2));
        float d2A, d2B;
        asm("mov.b64 {%0, %1}, %2;" : "=f"(d2A), "=f"(d2B) : "l"(d2));
        const float dA = fsqrt_approx(d2A);    // = K * dist  (only MUFU in loop)
        const float dB = fsqrt_approx(d2B);
        accA += exp2_fma(-dA);                 // exp(-256*dist) on FMA pipe
        accB += exp2_fma(-dB);
    }

    const float md = flog2_approx(accA + accB) * (-0.69314718f / 256.0f);
    const float z  = (0.04f - md) * (200.0f * 1.44269504f);
    out[p] = frcp_approx(1.0f + fexp2_approx(z));
}

extern "C" void kernel_launch(void* const* d_in, const int* in_sizes, int n_in,
                              void* d_out, int out_size) {
    const float* cp = (const float*)d_in[0];   // control_points [8,4,2]
    float* out = (float*)d_out;
    glyph_kernel<<<2048, NT>>>(cp, out);       // 2048 CTAs x 4 warp-tiles
}